// round 6
// baseline (speedup 1.0000x reference)
#include <cuda_runtime.h>
#include <cstdint>

// RoPE3DEncoder: T=32, H=64, W=64, DIM=192 (DIM_X=DIM_Y=DIM_T=64).
// Single 64-pos x 64-col cos/sin table (compile-time constexpr) covers all
// three axes. Output: cos [131072 x 192] f32 followed by sin.
// Write-stream kernel: one 256-bit streaming store (st.global.cs.v8.f32,
// Blackwell STG.E.256) per table per thread -> half the l1tex store
// instruction overhead of the float4 version, 1KB contiguous runs per warp.

#define ROWS 131072                 // 32*64*64
#define NQ8  (ROWS * 24)            // 8-float octets per table
#define TBL_FLOATS (ROWS * 192)     // floats per table (cos or sin)

// ---------------- compile-time math ----------------
constexpr double K_PI  = 3.14159265358979323846264338327950288;
constexpr double K_LN2 = 0.69314718055994530941723212145818;

constexpr double cexp(double x) {
    int n = 0; double y = x;
    while (y < -0.35) { y += K_LN2; n--; }
    while (y >  0.35) { y -= K_LN2; n++; }
    double term = 1.0, s = 1.0;
    for (int i = 1; i < 26; i++) { term *= y / i; s += term; }
    while (n < 0) { s *= 0.5; n++; }
    while (n > 0) { s *= 2.0; n--; }
    return s;
}
constexpr double csin(double x) {
    double tp = 2.0 * K_PI;
    long long k = (long long)(x / tp + 0.5);
    double y = x - (double)k * tp;
    double y2 = y * y, term = y, s = y;
    for (int i = 1; i < 16; i++) {
        term *= -y2 / (double)((2 * i) * (2 * i + 1));
        s += term;
    }
    return s;
}
constexpr double ccos(double x) { return csin(x + K_PI * 0.5); }

struct alignas(32) Tab { float c[64 * 64]; float s[64 * 64]; };

constexpr Tab make_tab() {
    Tab t{};
    for (int pos = 0; pos < 64; pos++) {
        for (int j = 0; j < 32; j++) {
            float invf = (float)cexp(-9.210340371976184 * (double)j / 32.0);
            float ang  = (float)pos * invf;       // match reference f32 pipeline
            float cv = (float)ccos((double)ang);
            float sv = (float)csin((double)ang);
            t.c[pos * 64 + j]      = cv;
            t.c[pos * 64 + j + 32] = cv;
            t.s[pos * 64 + j]      = sv;
            t.s[pos * 64 + j + 32] = sv;
        }
    }
    return t;
}

constexpr Tab H_TAB = make_tab();
__device__ const Tab g_tab = H_TAB;

// ---------------- fill kernel ----------------
__global__ void __launch_bounds__(256) rope_fill(float* __restrict__ out) {
    unsigned idx = blockIdx.x * blockDim.x + threadIdx.x;   // octet index
    unsigned row = idx / 24u;
    unsigned o   = idx - row * 24u;
    unsigned c8  = o * 8u;                 // starting column of this octet

    unsigned w = row & 63u;
    unsigned h = (row >> 6) & 63u;
    unsigned t = row >> 12;

    // Octets never straddle the 64/128 axis boundaries (64 % 8 == 0).
    unsigned pos = (c8 < 64u) ? w : ((c8 < 128u) ? h : t);
    unsigned off = pos * 64u + (c8 & 63u);         // float offset, 32B-aligned

    const float4* tc = reinterpret_cast<const float4*>(g_tab.c + off);
    const float4* ts = reinterpret_cast<const float4*>(g_tab.s + off);
    float4 c0 = tc[0], c1 = tc[1];
    float4 s0 = ts[0], s1 = ts[1];

    float* pc = out + (size_t)idx * 8u;            // cos half, 32B-aligned
    float* ps = pc + (size_t)TBL_FLOATS;           // sin half

    asm volatile(
        "st.global.cs.v8.f32 [%0], {%1, %2, %3, %4, %5, %6, %7, %8};"
        :: "l"(pc),
           "f"(c0.x), "f"(c0.y), "f"(c0.z), "f"(c0.w),
           "f"(c1.x), "f"(c1.y), "f"(c1.z), "f"(c1.w)
        : "memory");
    asm volatile(
        "st.global.cs.v8.f32 [%0], {%1, %2, %3, %4, %5, %6, %7, %8};"
        :: "l"(ps),
           "f"(s0.x), "f"(s0.y), "f"(s0.z), "f"(s0.w),
           "f"(s1.x), "f"(s1.y), "f"(s1.z), "f"(s1.w)
        : "memory");
}

extern "C" void kernel_launch(void* const* d_in, const int* in_sizes, int n_in,
                              void* d_out, int out_size) {
    (void)d_in; (void)in_sizes; (void)n_in; (void)out_size;
    // 3,145,728 octets / 256 = 12288 blocks, exact
    rope_fill<<<NQ8 / 256, 256>>>(reinterpret_cast<float*>(d_out));
}